// round 10
// baseline (speedup 1.0000x reference)
#include <cuda_runtime.h>
#include <cuda_fp16.h>
#include <cstdint>

// ---------------------------------------------------------------------------
// SimpleGCN on B200, round 10 (resubmit of R9; R9 died on container infra):
//   - ELL edge storage: edata[dst*64 + cur++] = src  (no histogram, no scan,
//     no offset pass; 4B records; deg == cursor after fill)
//   - dinv computed in gemm1 epilogue; cursor reset fused into gather3
//   - 8 launches: detect(0) fill(1) gemm1(2) gather1(3) gemm2(4) gather2(5)
//     gemm3(6) gather3(7)  ->  profiled slot lands on a gather
//   - gather: R4 layout (fp32 h, 16 thr/node, unroll 4), int4 index loads
//   - gemm: packed fma.rn.f32x2
// ---------------------------------------------------------------------------

#define MAXN (1 << 17)
#define FDIM 64
#define ESTRIDE 64    // max in-degree slots per node (Poisson(16): P(>64)~1e-20)

__device__ float g_h[(size_t)MAXN * FDIM];
__device__ float g_acc[(size_t)MAXN * FDIM];
__device__ float g_dinv[MAXN];
__device__ int   g_cur[MAXN];                    // zero-init; reset by gather3
__device__ int   g_eidx[(size_t)MAXN * ESTRIDE]; // ELL: src indices
__device__ int   g_is64;

// --- packed f32x2 helpers ---
__device__ __forceinline__ unsigned long long ffma2(
    unsigned long long a, unsigned long long b, unsigned long long c) {
    unsigned long long d;
    asm("fma.rn.f32x2 %0, %1, %2, %3;" : "=l"(d) : "l"(a), "l"(b), "l"(c));
    return d;
}
__device__ __forceinline__ unsigned long long pack2(float x) {
    unsigned long long p;
    asm("mov.b64 %0, {%1, %1};" : "=l"(p) : "f"(x));
    return p;
}
__device__ __forceinline__ float2 unpack2(unsigned long long p) {
    float lo, hi;
    asm("mov.b64 {%0, %1}, %2;" : "=f"(lo), "=f"(hi) : "l"(p));
    return make_float2(lo, hi);
}

// --- launch 0: dtype detect (int64 LE small values -> odd words zero)
__global__ void k_detect(const unsigned int* __restrict__ w, long long nwords) {
    __shared__ int cnt;
    if (threadIdx.x == 0) cnt = 0;
    __syncthreads();
    int zeros = 0;
    for (long long i = threadIdx.x; i < 2048 && i < nwords; i += blockDim.x)
        if ((i & 1) && w[i] == 0u) zeros++;
    atomicAdd(&cnt, zeros);
    __syncthreads();
    if (threadIdx.x == 0) g_is64 = (cnt > 512) ? 1 : 0;
}

// --- launch 1: ELL fill. cur[] is zero (init or reset by prior gather3).
__global__ void k_fill(const void* __restrict__ e, long long E) {
    long long i = (long long)blockIdx.x * blockDim.x + threadIdx.x;
    if (i >= E) return;
    int s, d;
    if (g_is64) {
        const long long* p = (const long long*)e;
        s = (int)p[i]; d = (int)p[E + i];
    } else {
        const int* p = (const int*)e;
        s = p[i]; d = p[E + i];
    }
    int t = atomicAdd(&g_cur[d], 1);
    if (t < ESTRIDE) g_eidx[(size_t)d * ESTRIDE + t] = s;
}

// --- GEMM: h = act(in) @ W via packed f32x2; DINV: also emit dinv[r]
template <int LRELU, int DINV>
__global__ void __launch_bounds__(128)
k_gemm(const float* __restrict__ in, const float* __restrict__ W,
       float* __restrict__ h, int n) {
    __shared__ float Ws[FDIM * FDIM];
    for (int i = threadIdx.x; i < FDIM * FDIM; i += blockDim.x) Ws[i] = W[i];
    __syncthreads();

    int r = blockIdx.x * blockDim.x + threadIdx.x;
    if (r >= n) return;

    if (DINV) {
        int deg = g_cur[r];
        if (deg > ESTRIDE) deg = ESTRIDE;
        g_dinv[r] = rsqrtf((float)(1 + deg));   // +1 self loop
    }

    unsigned long long acc2[FDIM / 2];
#pragma unroll
    for (int j = 0; j < FDIM / 2; j++) acc2[j] = 0ull;

    const float4* x4 = (const float4*)(in + (size_t)r * FDIM);
#pragma unroll 4
    for (int k4 = 0; k4 < FDIM / 4; k4++) {
        float4 xv = __ldg(x4 + k4);
        float xs[4] = {xv.x, xv.y, xv.z, xv.w};
#pragma unroll
        for (int kk = 0; kk < 4; kk++) {
            float xk = xs[kk];
            if (LRELU) xk = xk > 0.0f ? xk : 0.01f * xk;
            unsigned long long xk2 = pack2(xk);
            const ulonglong2* Wr = (const ulonglong2*)&Ws[(k4 * 4 + kk) * FDIM];
#pragma unroll
            for (int j = 0; j < FDIM / 4; j++) {
                ulonglong2 w2 = Wr[j];
                acc2[2 * j]     = ffma2(xk2, w2.x, acc2[2 * j]);
                acc2[2 * j + 1] = ffma2(xk2, w2.y, acc2[2 * j + 1]);
            }
        }
    }

    float4* hr = (float4*)(h + (size_t)r * FDIM);
#pragma unroll
    for (int j = 0; j < FDIM / 4; j++) {
        float2 lo = unpack2(acc2[2 * j]);
        float2 hi = unpack2(acc2[2 * j + 1]);
        hr[j] = make_float4(lo.x, lo.y, hi.x, hi.y);
    }
}

// --- ELL gather: 16 threads/node, one float4 col slab each, unroll-4.
//     out[i] = sum_e h[src_e]*dinv[s]*dinv[i] + h[i]*dinv[i]^2 + b
//     RESET: zero g_cur[node] for the next replay (after reading it).
template <int RESET>
__global__ void __launch_bounds__(256)
k_gather(const float* __restrict__ h, float* __restrict__ out,
         const float* __restrict__ b, int n) {
    int node = blockIdx.x * 16 + (threadIdx.x >> 4);
    if (node >= n) return;
    int c4 = threadIdx.x & 15;               // float4 column slab index

    int deg = g_cur[node];                   // half-warp reads, then lane0 resets
    if (RESET && (threadIdx.x & 15) == 0) g_cur[node] = 0;
    if (deg > ESTRIDE) deg = ESTRIDE;

    const float4* h4 = (const float4*)h;
    float di = g_dinv[node];
    float sn = di * di;

    float4 self = h4[(size_t)node * 16 + c4];
    float4 bv   = __ldg((const float4*)b + c4);
    float4 a;
    a.x = fmaf(self.x, sn, bv.x);
    a.y = fmaf(self.y, sn, bv.y);
    a.z = fmaf(self.z, sn, bv.z);
    a.w = fmaf(self.w, sn, bv.w);

    const int* ed = g_eidx + (size_t)node * ESTRIDE;
    int e = 0;
    for (; e + 4 <= deg; e += 4) {
        int4 s4 = *(const int4*)(ed + e);    // broadcast across half-warp
        float4 v0 = h4[(size_t)s4.x * 16 + c4];
        float4 v1 = h4[(size_t)s4.y * 16 + c4];
        float4 v2 = h4[(size_t)s4.z * 16 + c4];
        float4 v3 = h4[(size_t)s4.w * 16 + c4];
        float n0 = g_dinv[s4.x] * di;
        float n1 = g_dinv[s4.y] * di;
        float n2 = g_dinv[s4.z] * di;
        float n3 = g_dinv[s4.w] * di;
        a.x = fmaf(v0.x, n0, a.x); a.y = fmaf(v0.y, n0, a.y);
        a.z = fmaf(v0.z, n0, a.z); a.w = fmaf(v0.w, n0, a.w);
        a.x = fmaf(v1.x, n1, a.x); a.y = fmaf(v1.y, n1, a.y);
        a.z = fmaf(v1.z, n1, a.z); a.w = fmaf(v1.w, n1, a.w);
        a.x = fmaf(v2.x, n2, a.x); a.y = fmaf(v2.y, n2, a.y);
        a.z = fmaf(v2.z, n2, a.z); a.w = fmaf(v2.w, n2, a.w);
        a.x = fmaf(v3.x, n3, a.x); a.y = fmaf(v3.y, n3, a.y);
        a.z = fmaf(v3.z, n3, a.z); a.w = fmaf(v3.w, n3, a.w);
    }
    for (; e < deg; e++) {
        int s = ed[e];
        float4 v = h4[(size_t)s * 16 + c4];
        float nn = g_dinv[s] * di;
        a.x = fmaf(v.x, nn, a.x); a.y = fmaf(v.y, nn, a.y);
        a.z = fmaf(v.z, nn, a.z); a.w = fmaf(v.w, nn, a.w);
    }

    ((float4*)out)[(size_t)node * 16 + c4] = a;
}

extern "C" void kernel_launch(void* const* d_in, const int* in_sizes, int n_in,
                              void* d_out, int out_size) {
    const float* x  = (const float*)d_in[0];
    const void*  ei = d_in[1];
    const float* W1 = (const float*)d_in[2];
    const float* b1 = (const float*)d_in[3];
    const float* W2 = (const float*)d_in[4];
    const float* b2 = (const float*)d_in[5];
    const float* W3 = (const float*)d_in[6];
    const float* b3 = (const float*)d_in[7];
    float* out = (float*)d_out;

    int n = in_sizes[0] / FDIM;
    long long E = (long long)in_sizes[1] / 2;

    float *hbuf, *accbuf;
    cudaGetSymbolAddress((void**)&hbuf, g_h);
    cudaGetSymbolAddress((void**)&accbuf, g_acc);

    int nb_e  = (int)((E + 255) / 256);
    int nb_g  = (n + 127) / 128;
    int nb_ga = (n + 15) / 16;

    k_detect<<<1, 256>>>((const unsigned int*)ei, 2 * E);       // 0
    k_fill<<<nb_e, 256>>>(ei, E);                               // 1
    k_gemm<0, 1><<<nb_g, 128>>>(x, W1, hbuf, n);                // 2 (+dinv)
    k_gather<0><<<nb_ga, 256>>>(hbuf, accbuf, b1, n);           // 3 <- profiled
    k_gemm<1, 0><<<nb_g, 128>>>(accbuf, W2, hbuf, n);           // 4
    k_gather<0><<<nb_ga, 256>>>(hbuf, accbuf, b2, n);           // 5 (alt slot)
    k_gemm<1, 0><<<nb_g, 128>>>(accbuf, W3, hbuf, n);           // 6
    k_gather<1><<<nb_ga, 256>>>(hbuf, out, b3, n);              // 7 (+reset)
}

// round 11
// speedup vs baseline: 1.2142x; 1.2142x over previous
#include <cuda_runtime.h>
#include <cuda_fp16.h>
#include <cstdint>

// ---------------------------------------------------------------------------
// SimpleGCN on B200, round 11: R8 skeleton (proven 326us) + shfl-gather.
//   prep: scan-free CSR {src,norm} (fill measured 35.6us, L2=72%)
//   gather: per 16-edge block, lane l loads ed[base+l] once (coalesced),
//           records distributed via width-16 shfl -> 16x fewer record LDGs,
//           record->h dependency goes L2-latency(250cyc) -> shfl(26cyc).
//   gemm: packed fma.rn.f32x2.
// ---------------------------------------------------------------------------

#define MAXN (1 << 17)
#define MAXE (1 << 21)
#define FDIM 64

__device__ float g_h[(size_t)MAXN * FDIM];
__device__ float g_acc[(size_t)MAXN * FDIM];
__device__ float g_dinv[MAXN];
__device__ int   g_cnt[MAXN];
__device__ int   g_row[MAXN];
__device__ int   g_cur[MAXN];
__device__ int   g_total;
__device__ int2  g_edata[MAXE];
__device__ int   g_is64;

// --- packed f32x2 helpers ---
__device__ __forceinline__ unsigned long long ffma2(
    unsigned long long a, unsigned long long b, unsigned long long c) {
    unsigned long long d;
    asm("fma.rn.f32x2 %0, %1, %2, %3;" : "=l"(d) : "l"(a), "l"(b), "l"(c));
    return d;
}
__device__ __forceinline__ unsigned long long pack2(float x) {
    unsigned long long p;
    asm("mov.b64 %0, {%1, %1};" : "=l"(p) : "f"(x));
    return p;
}
__device__ __forceinline__ float2 unpack2(unsigned long long p) {
    float lo, hi;
    asm("mov.b64 {%0, %1}, %2;" : "=f"(lo), "=f"(hi) : "l"(p));
    return make_float2(lo, hi);
}

// --- launch 0: dtype detect + zero counters
__global__ void k_prep0(const unsigned int* __restrict__ w, long long nwords, int n) {
    int i = blockIdx.x * blockDim.x + threadIdx.x;
    if (i < n) { g_cnt[i] = 0; g_cur[i] = 0; }
    if (i == 0) g_total = 0;
    if (blockIdx.x == 0) {
        __shared__ int cnt;
        if (threadIdx.x == 0) cnt = 0;
        __syncthreads();
        int zeros = 0;
        for (long long j = threadIdx.x; j < 2048 && j < nwords; j += blockDim.x)
            if ((j & 1) && w[j] == 0u) zeros++;
        atomicAdd(&cnt, zeros);
        __syncthreads();
        if (threadIdx.x == 0) g_is64 = (cnt > 512) ? 1 : 0;
    }
}

__device__ __forceinline__ int load_idx(const void* e, long long pos) {
    if (g_is64) return (int)((const long long*)e)[pos];
    return ((const int*)e)[pos];
}

// --- launch 1: in-degree histogram
__global__ void k_deg(const void* __restrict__ e, long long E) {
    long long i = (long long)blockIdx.x * blockDim.x + threadIdx.x;
    if (i >= E) return;
    atomicAdd(&g_cnt[load_idx(e, E + i)], 1);
}

// --- launch 2: dinv + unordered disjoint CSR range allocation
__global__ void k_dinv_alloc(int n) {
    int i = blockIdx.x * blockDim.x + threadIdx.x;
    if (i >= n) return;
    int c = g_cnt[i];
    g_dinv[i] = rsqrtf((float)(1 + c));   // +1 self loop
    g_row[i] = atomicAdd(&g_total, c);
}

// --- launch 3: CSR fill {src, norm}
__global__ void k_fill(const void* __restrict__ e, long long E) {
    long long i = (long long)blockIdx.x * blockDim.x + threadIdx.x;
    if (i >= E) return;
    int s, d;
    if (g_is64) {
        const long long* p = (const long long*)e;
        s = (int)p[i]; d = (int)p[E + i];
    } else {
        const int* p = (const int*)e;
        s = p[i]; d = p[E + i];
    }
    int pos = g_row[d] + atomicAdd(&g_cur[d], 1);
    g_edata[pos] = make_int2(s, __float_as_int(g_dinv[s] * g_dinv[d]));
}

// --- GEMM: h = act(in) @ W via packed f32x2
template <int LRELU>
__global__ void __launch_bounds__(128)
k_gemm(const float* __restrict__ in, const float* __restrict__ W,
       float* __restrict__ h, int n) {
    __shared__ float Ws[FDIM * FDIM];
    for (int i = threadIdx.x; i < FDIM * FDIM; i += blockDim.x) Ws[i] = W[i];
    __syncthreads();

    int r = blockIdx.x * blockDim.x + threadIdx.x;
    if (r >= n) return;

    unsigned long long acc2[FDIM / 2];
#pragma unroll
    for (int j = 0; j < FDIM / 2; j++) acc2[j] = 0ull;

    const float4* x4 = (const float4*)(in + (size_t)r * FDIM);
#pragma unroll 4
    for (int k4 = 0; k4 < FDIM / 4; k4++) {
        float4 xv = __ldg(x4 + k4);
        float xs[4] = {xv.x, xv.y, xv.z, xv.w};
#pragma unroll
        for (int kk = 0; kk < 4; kk++) {
            float xk = xs[kk];
            if (LRELU) xk = xk > 0.0f ? xk : 0.01f * xk;
            unsigned long long xk2 = pack2(xk);
            const ulonglong2* Wr = (const ulonglong2*)&Ws[(k4 * 4 + kk) * FDIM];
#pragma unroll
            for (int j = 0; j < FDIM / 4; j++) {
                ulonglong2 w2 = Wr[j];
                acc2[2 * j]     = ffma2(xk2, w2.x, acc2[2 * j]);
                acc2[2 * j + 1] = ffma2(xk2, w2.y, acc2[2 * j + 1]);
            }
        }
    }

    float4* hr = (float4*)(h + (size_t)r * FDIM);
#pragma unroll
    for (int j = 0; j < FDIM / 4; j++) {
        float2 lo = unpack2(acc2[2 * j]);
        float2 hi = unpack2(acc2[2 * j + 1]);
        hr[j] = make_float4(lo.x, lo.y, hi.x, hi.y);
    }
}

// --- CSR gather, shfl-broadcast records.
//     16 lanes/node; per 16-edge block: lane l loads ed[base+l] (coalesced),
//     then width-16 shfl distributes {src, norm} to all lanes.
__global__ void __launch_bounds__(256)
k_gather(const float* __restrict__ h, float* __restrict__ out,
         const float* __restrict__ b, int n) {
    int node = blockIdx.x * 16 + (threadIdx.x >> 4);
    int l16  = threadIdx.x & 15;
    unsigned hmask = 0xFFFFu << (threadIdx.x & 16);   // this half-warp's lanes

    bool valid = node < n;
    int nodec = valid ? node : (n > 0 ? n - 1 : 0);

    int start = g_row[nodec];
    int deg   = g_cnt[nodec];
    float di  = g_dinv[nodec];
    float sn  = di * di;

    const float4* h4 = (const float4*)h;
    float4 self = h4[(size_t)nodec * 16 + l16];
    float4 bv   = __ldg((const float4*)b + l16);
    float4 a;
    a.x = fmaf(self.x, sn, bv.x);
    a.y = fmaf(self.y, sn, bv.y);
    a.z = fmaf(self.z, sn, bv.z);
    a.w = fmaf(self.w, sn, bv.w);

    const int2* ed = g_edata + start;
    for (int base = 0; base < deg; base += 16) {
        int rem = deg - base;
        int m = rem < 16 ? rem : 16;
        int2 rec = (l16 < m) ? ed[base + l16] : make_int2(0, 0);

        int i = 0;
        for (; i + 4 <= m; i += 4) {
            int   s0 = __shfl_sync(hmask, rec.x, i,     16);
            int   s1 = __shfl_sync(hmask, rec.x, i + 1, 16);
            int   s2 = __shfl_sync(hmask, rec.x, i + 2, 16);
            int   s3 = __shfl_sync(hmask, rec.x, i + 3, 16);
            float n0 = __int_as_float(__shfl_sync(hmask, rec.y, i,     16));
            float n1 = __int_as_float(__shfl_sync(hmask, rec.y, i + 1, 16));
            float n2 = __int_as_float(__shfl_sync(hmask, rec.y, i + 2, 16));
            float n3 = __int_as_float(__shfl_sync(hmask, rec.y, i + 3, 16));
            float4 v0 = h4[(size_t)s0 * 16 + l16];
            float4 v1 = h4[(size_t)s1 * 16 + l16];
            float4 v2 = h4[(size_t)s2 * 16 + l16];
            float4 v3 = h4[(size_t)s3 * 16 + l16];
            a.x = fmaf(v0.x, n0, a.x); a.y = fmaf(v0.y, n0, a.y);
            a.z = fmaf(v0.z, n0, a.z); a.w = fmaf(v0.w, n0, a.w);
            a.x = fmaf(v1.x, n1, a.x); a.y = fmaf(v1.y, n1, a.y);
            a.z = fmaf(v1.z, n1, a.z); a.w = fmaf(v1.w, n1, a.w);
            a.x = fmaf(v2.x, n2, a.x); a.y = fmaf(v2.y, n2, a.y);
            a.z = fmaf(v2.z, n2, a.z); a.w = fmaf(v2.w, n2, a.w);
            a.x = fmaf(v3.x, n3, a.x); a.y = fmaf(v3.y, n3, a.y);
            a.z = fmaf(v3.z, n3, a.z); a.w = fmaf(v3.w, n3, a.w);
        }
        for (; i < m; i++) {
            int   s = __shfl_sync(hmask, rec.x, i, 16);
            float nn = __int_as_float(__shfl_sync(hmask, rec.y, i, 16));
            float4 v = h4[(size_t)s * 16 + l16];
            a.x = fmaf(v.x, nn, a.x); a.y = fmaf(v.y, nn, a.y);
            a.z = fmaf(v.z, nn, a.z); a.w = fmaf(v.w, nn, a.w);
        }
    }

    if (valid)
        ((float4*)out)[(size_t)node * 16 + l16] = a;
}

extern "C" void kernel_launch(void* const* d_in, const int* in_sizes, int n_in,
                              void* d_out, int out_size) {
    const float* x  = (const float*)d_in[0];
    const void*  ei = d_in[1];
    const float* W1 = (const float*)d_in[2];
    const float* b1 = (const float*)d_in[3];
    const float* W2 = (const float*)d_in[4];
    const float* b2 = (const float*)d_in[5];
    const float* W3 = (const float*)d_in[6];
    const float* b3 = (const float*)d_in[7];
    float* out = (float*)d_out;

    int n = in_sizes[0] / FDIM;
    long long E = (long long)in_sizes[1] / 2;

    float *hbuf, *accbuf;
    cudaGetSymbolAddress((void**)&hbuf, g_h);
    cudaGetSymbolAddress((void**)&accbuf, g_acc);

    int nb_n  = (n + 255) / 256;
    int nb_e  = (int)((E + 255) / 256);
    int nb_g  = (n + 127) / 128;
    int nb_ga = (n + 15) / 16;

    k_prep0<<<nb_n, 256>>>((const unsigned int*)ei, 2 * E, n);  // 0
    k_deg<<<nb_e, 256>>>(ei, E);                                // 1
    k_dinv_alloc<<<nb_n, 256>>>(n);                             // 2
    k_fill<<<nb_e, 256>>>(ei, E);                               // 3 <- profiled
    k_gemm<0><<<nb_g, 128>>>(x, W1, hbuf, n);                   // 4
    k_gather<<<nb_ga, 256>>>(hbuf, accbuf, b1, n);              // 5
    k_gemm<1><<<nb_g, 128>>>(accbuf, W2, hbuf, n);              // 6
    k_gather<<<nb_ga, 256>>>(hbuf, accbuf, b2, n);              // 7
    k_gemm<1><<<nb_g, 128>>>(accbuf, W3, hbuf, n);              // 8
    k_gather<<<nb_ga, 256>>>(hbuf, out, b3, n);                 // 9
}

// round 12
// speedup vs baseline: 1.4751x; 1.2149x over previous
#include <cuda_runtime.h>
#include <cuda_fp16.h>
#include <cstdint>

// ---------------------------------------------------------------------------
// SimpleGCN on B200, round 12: R8 skeleton + fp16 h at FIXED 16-lane layout.
//   (R6's fp16 regression was confounded by an 8-lane layout; this isolates
//    bytes at the proven parallelism. h row: 256B -> 128B = 1 L1 wavefront.)
//   prep: scan-free CSR {src,norm} (fill = 35.6us canary at launch idx 3)
//   gather: 16 lanes/node, lane owns 4 cols (8B uint2), direct record loads.
//   gemm: packed fma.rn.f32x2, fp16 epilogue.
// ---------------------------------------------------------------------------

#define MAXN (1 << 17)
#define MAXE (1 << 21)
#define FDIM 64

__device__ __half g_h[(size_t)MAXN * FDIM];      // fp16 transformed features
__device__ float  g_acc[(size_t)MAXN * FDIM];    // fp32 layer outputs
__device__ float  g_dinv[MAXN];
__device__ int    g_cnt[MAXN];
__device__ int    g_row[MAXN];
__device__ int    g_cur[MAXN];
__device__ int    g_total;
__device__ int2   g_edata[MAXE];
__device__ int    g_is64;

// --- packed f32x2 helpers ---
__device__ __forceinline__ unsigned long long ffma2(
    unsigned long long a, unsigned long long b, unsigned long long c) {
    unsigned long long d;
    asm("fma.rn.f32x2 %0, %1, %2, %3;" : "=l"(d) : "l"(a), "l"(b), "l"(c));
    return d;
}
__device__ __forceinline__ unsigned long long pack2(float x) {
    unsigned long long p;
    asm("mov.b64 %0, {%1, %1};" : "=l"(p) : "f"(x));
    return p;
}
__device__ __forceinline__ float2 unpack2(unsigned long long p) {
    float lo, hi;
    asm("mov.b64 {%0, %1}, %2;" : "=f"(lo), "=f"(hi) : "l"(p));
    return make_float2(lo, hi);
}
__device__ __forceinline__ uint32_t h2_as_u32(__half2 v) {
    return *reinterpret_cast<uint32_t*>(&v);
}

// --- launch 0: dtype detect + zero counters
__global__ void k_prep0(const unsigned int* __restrict__ w, long long nwords, int n) {
    int i = blockIdx.x * blockDim.x + threadIdx.x;
    if (i < n) { g_cnt[i] = 0; g_cur[i] = 0; }
    if (i == 0) g_total = 0;
    if (blockIdx.x == 0) {
        __shared__ int cnt;
        if (threadIdx.x == 0) cnt = 0;
        __syncthreads();
        int zeros = 0;
        for (long long j = threadIdx.x; j < 2048 && j < nwords; j += blockDim.x)
            if ((j & 1) && w[j] == 0u) zeros++;
        atomicAdd(&cnt, zeros);
        __syncthreads();
        if (threadIdx.x == 0) g_is64 = (cnt > 512) ? 1 : 0;
    }
}

__device__ __forceinline__ int load_idx(const void* e, long long pos) {
    if (g_is64) return (int)((const long long*)e)[pos];
    return ((const int*)e)[pos];
}

// --- launch 1: in-degree histogram
__global__ void k_deg(const void* __restrict__ e, long long E) {
    long long i = (long long)blockIdx.x * blockDim.x + threadIdx.x;
    if (i >= E) return;
    atomicAdd(&g_cnt[load_idx(e, E + i)], 1);
}

// --- launch 2: dinv + unordered disjoint CSR range allocation
__global__ void k_dinv_alloc(int n) {
    int i = blockIdx.x * blockDim.x + threadIdx.x;
    if (i >= n) return;
    int c = g_cnt[i];
    g_dinv[i] = rsqrtf((float)(1 + c));   // +1 self loop
    g_row[i] = atomicAdd(&g_total, c);
}

// --- launch 3: CSR fill {src, norm}   <- profiled slot (canary: 35.6us)
__global__ void k_fill(const void* __restrict__ e, long long E) {
    long long i = (long long)blockIdx.x * blockDim.x + threadIdx.x;
    if (i >= E) return;
    int s, d;
    if (g_is64) {
        const long long* p = (const long long*)e;
        s = (int)p[i]; d = (int)p[E + i];
    } else {
        const int* p = (const int*)e;
        s = p[i]; d = p[E + i];
    }
    int pos = g_row[d] + atomicAdd(&g_cur[d], 1);
    g_edata[pos] = make_int2(s, __float_as_int(g_dinv[s] * g_dinv[d]));
}

// --- GEMM: h = act(in) @ W via packed f32x2; fp16 epilogue
template <int LRELU>
__global__ void __launch_bounds__(128)
k_gemm(const float* __restrict__ in, const float* __restrict__ W,
       __half* __restrict__ h, int n) {
    __shared__ float Ws[FDIM * FDIM];
    for (int i = threadIdx.x; i < FDIM * FDIM; i += blockDim.x) Ws[i] = W[i];
    __syncthreads();

    int r = blockIdx.x * blockDim.x + threadIdx.x;
    if (r >= n) return;

    unsigned long long acc2[FDIM / 2];
#pragma unroll
    for (int j = 0; j < FDIM / 2; j++) acc2[j] = 0ull;

    const float4* x4 = (const float4*)(in + (size_t)r * FDIM);
#pragma unroll 4
    for (int k4 = 0; k4 < FDIM / 4; k4++) {
        float4 xv = __ldg(x4 + k4);
        float xs[4] = {xv.x, xv.y, xv.z, xv.w};
#pragma unroll
        for (int kk = 0; kk < 4; kk++) {
            float xk = xs[kk];
            if (LRELU) xk = xk > 0.0f ? xk : 0.01f * xk;
            unsigned long long xk2 = pack2(xk);
            const ulonglong2* Wr = (const ulonglong2*)&Ws[(k4 * 4 + kk) * FDIM];
#pragma unroll
            for (int j = 0; j < FDIM / 4; j++) {
                ulonglong2 w2 = Wr[j];
                acc2[2 * j]     = ffma2(xk2, w2.x, acc2[2 * j]);
                acc2[2 * j + 1] = ffma2(xk2, w2.y, acc2[2 * j + 1]);
            }
        }
    }

    // epilogue: 64 halves = 8 x 16B stores
    uint4* hr = (uint4*)(h + (size_t)r * FDIM);
#pragma unroll
    for (int j = 0; j < 8; j++) {
        float2 p0 = unpack2(acc2[4 * j + 0]);
        float2 p1 = unpack2(acc2[4 * j + 1]);
        float2 p2 = unpack2(acc2[4 * j + 2]);
        float2 p3 = unpack2(acc2[4 * j + 3]);
        uint4 v;
        v.x = h2_as_u32(__floats2half2_rn(p0.x, p0.y));
        v.y = h2_as_u32(__floats2half2_rn(p1.x, p1.y));
        v.z = h2_as_u32(__floats2half2_rn(p2.x, p2.y));
        v.w = h2_as_u32(__floats2half2_rn(p3.x, p3.y));
        hr[j] = v;
    }
}

// --- CSR gather: 16 lanes/node, lane owns 4 cols (uint2 = 4 halves = 8B).
//     Direct record loads (R8 structure — shfl variant measured slower).
__device__ __forceinline__ void acc_u2(uint2 u, float nn, float4& a) {
    __half2 h0 = *reinterpret_cast<__half2*>(&u.x);
    __half2 h1 = *reinterpret_cast<__half2*>(&u.y);
    float2 f0 = __half22float2(h0);
    float2 f1 = __half22float2(h1);
    a.x = fmaf(f0.x, nn, a.x); a.y = fmaf(f0.y, nn, a.y);
    a.z = fmaf(f1.x, nn, a.z); a.w = fmaf(f1.y, nn, a.w);
}

__global__ void __launch_bounds__(256)
k_gather(const __half* __restrict__ h, float* __restrict__ out,
         const float* __restrict__ b, int n) {
    int node = blockIdx.x * 16 + (threadIdx.x >> 4);
    if (node >= n) return;
    int l16 = threadIdx.x & 15;              // owns cols [4*l16, 4*l16+4)

    const uint2* h2 = (const uint2*)h;       // 16 uint2 per row
    int start = g_row[node];
    int deg   = g_cnt[node];
    float di  = g_dinv[node];
    float sn  = di * di;

    float4 a = __ldg((const float4*)b + l16);
    acc_u2(h2[(size_t)node * 16 + l16], sn, a);   // self loop

    const int2* ed = g_edata + start;
    int e = 0;
    for (; e + 4 <= deg; e += 4) {
        int2 e0 = ed[e], e1 = ed[e + 1], e2 = ed[e + 2], e3 = ed[e + 3];
        uint2 v0 = h2[(size_t)e0.x * 16 + l16];
        uint2 v1 = h2[(size_t)e1.x * 16 + l16];
        uint2 v2 = h2[(size_t)e2.x * 16 + l16];
        uint2 v3 = h2[(size_t)e3.x * 16 + l16];
        acc_u2(v0, __int_as_float(e0.y), a);
        acc_u2(v1, __int_as_float(e1.y), a);
        acc_u2(v2, __int_as_float(e2.y), a);
        acc_u2(v3, __int_as_float(e3.y), a);
    }
    for (; e < deg; e++) {
        int2 ee = ed[e];
        uint2 v = h2[(size_t)ee.x * 16 + l16];
        acc_u2(v, __int_as_float(ee.y), a);
    }

    ((float4*)out)[(size_t)node * 16 + l16] = a;
}

extern "C" void kernel_launch(void* const* d_in, const int* in_sizes, int n_in,
                              void* d_out, int out_size) {
    const float* x  = (const float*)d_in[0];
    const void*  ei = d_in[1];
    const float* W1 = (const float*)d_in[2];
    const float* b1 = (const float*)d_in[3];
    const float* W2 = (const float*)d_in[4];
    const float* b2 = (const float*)d_in[5];
    const float* W3 = (const float*)d_in[6];
    const float* b3 = (const float*)d_in[7];
    float* out = (float*)d_out;

    int n = in_sizes[0] / FDIM;
    long long E = (long long)in_sizes[1] / 2;

    __half* hbuf;
    float* accbuf;
    cudaGetSymbolAddress((void**)&hbuf, g_h);
    cudaGetSymbolAddress((void**)&accbuf, g_acc);

    int nb_n  = (n + 255) / 256;
    int nb_e  = (int)((E + 255) / 256);
    int nb_g  = (n + 127) / 128;
    int nb_ga = (n + 15) / 16;

    k_prep0<<<nb_n, 256>>>((const unsigned int*)ei, 2 * E, n);  // 0
    k_deg<<<nb_e, 256>>>(ei, E);                                // 1
    k_dinv_alloc<<<nb_n, 256>>>(n);                             // 2
    k_fill<<<nb_e, 256>>>(ei, E);                               // 3 <- profiled
    k_gemm<0><<<nb_g, 128>>>(x, W1, hbuf, n);                   // 4
    k_gather<<<nb_ga, 256>>>(hbuf, accbuf, b1, n);              // 5
    k_gemm<1><<<nb_g, 128>>>(accbuf, W2, hbuf, n);              // 6
    k_gather<<<nb_ga, 256>>>(hbuf, accbuf, b2, n);              // 7
    k_gemm<1><<<nb_g, 128>>>(accbuf, W3, hbuf, n);              // 8
    k_gather<<<nb_ga, 256>>>(hbuf, out, b3, n);                 // 9
}